// round 1
// baseline (speedup 1.0000x reference)
#include <cuda_runtime.h>

#define BSZ      8
#define SEQ      16
#define DMODEL   512
#define MAXSEQ   8192
#define SPOS     4096
#define KVLEN    4112
#define NROWS    (BSZ*SEQ)        // 128
#define ATT_SCALE 0.0625f          // (512/2)^-0.5
#define NSPLIT   9                 // kv split chunks of 512

// ---- scratch (static device globals; no allocation) ----
__device__ float g_q[NROWS*DMODEL];
__device__ float g_k[NROWS*DMODEL];
__device__ float g_v[NROWS*DMODEL];
__device__ float g_sc[(size_t)NROWS*KVLEN];              // masked scores -> probs (in place)
__device__ float g_part[(size_t)BSZ*4*NSPLIT*SEQ*128];   // PV partials
__device__ float g_att[NROWS*DMODEL];

// ============================================================
// Generic tile GEMM: C[m0+16][n0+128] = A[16x512] @ W[128x512]^T
// 64 threads, micro-tile 4x8, BK=16.
// ============================================================
__global__ void __launch_bounds__(64) gemm16x128(
    const float* __restrict__ A, const float* __restrict__ W,
    float* __restrict__ C, int ldc)
{
    __shared__ float As[DMODEL][17];   // transposed: As[d][m]
    __shared__ float Ws[16][132];      // Ws[j][p]
    const int tid = threadIdx.x;
    const int tx = tid & 15, ty = tid >> 4;
    const int m0 = blockIdx.y * 16, n0 = blockIdx.x * 128;

    for (int i = tid; i < 16*DMODEL; i += 64) {
        int m = i >> 9, d = i & 511;
        As[d][m] = A[(size_t)(m0+m)*DMODEL + d];
    }

    float acc[4][8];
#pragma unroll
    for (int a = 0; a < 4; a++)
#pragma unroll
        for (int b = 0; b < 8; b++) acc[a][b] = 0.f;

    const int jl = tid & 15;   // k-column within step
    const int pr = tid >> 4;   // starting row
    for (int kk = 0; kk < DMODEL; kk += 16) {
        __syncthreads();
        for (int p = pr; p < 128; p += 4)
            Ws[jl][p] = W[(size_t)(n0+p)*DMODEL + kk + jl];
        __syncthreads();
#pragma unroll
        for (int j = 0; j < 16; j++) {
            float av[4];
#pragma unroll
            for (int mi = 0; mi < 4; mi++) av[mi] = As[kk+j][ty*4+mi];
            float4 w0 = *(const float4*)&Ws[j][tx*8];
            float4 w1 = *(const float4*)&Ws[j][tx*8+4];
            float wv[8] = {w0.x,w0.y,w0.z,w0.w,w1.x,w1.y,w1.z,w1.w};
#pragma unroll
            for (int mi = 0; mi < 4; mi++)
#pragma unroll
                for (int ni = 0; ni < 8; ni++)
                    acc[mi][ni] += av[mi]*wv[ni];
        }
    }

#pragma unroll
    for (int mi = 0; mi < 4; mi++) {
        size_t base = (size_t)(m0 + ty*4 + mi)*ldc + n0 + tx*8;
        float4 o0 = make_float4(acc[mi][0],acc[mi][1],acc[mi][2],acc[mi][3]);
        float4 o1 = make_float4(acc[mi][4],acc[mi][5],acc[mi][6],acc[mi][7]);
        *(float4*)&C[base]   = o0;
        *(float4*)&C[base+4] = o1;
    }
}

// ============================================================
// Scores: dist[b][q][p] = (q . k_p) * scale ; writes weight (pre-mask)
// and masked scores to g_sc. K source: cache for p<SPOS, fresh k after.
// grid (33, 8), 64 threads, same tiling as gemm16x128.
// ============================================================
__global__ void __launch_bounds__(64) scores_kernel(
    const float* __restrict__ cache_k, const float* __restrict__ mask,
    float* __restrict__ weight_out)
{
    __shared__ float As[DMODEL][17];
    __shared__ float Ws[16][132];
    const int tid = threadIdx.x;
    const int tx = tid & 15, ty = tid >> 4;
    const int b  = blockIdx.y;
    const int p0 = blockIdx.x * 128;
    const float* A = g_q + (size_t)b*SEQ*DMODEL;

    for (int i = tid; i < 16*DMODEL; i += 64) {
        int m = i >> 9, d = i & 511;
        As[d][m] = A[(size_t)m*DMODEL + d];
    }

    float acc[4][8];
#pragma unroll
    for (int a = 0; a < 4; a++)
#pragma unroll
        for (int c = 0; c < 8; c++) acc[a][c] = 0.f;

    const int jl = tid & 15;
    const int pr = tid >> 4;
    for (int kk = 0; kk < DMODEL; kk += 16) {
        __syncthreads();
        for (int p = pr; p < 128; p += 4) {
            int gp = p0 + p;
            float v = 0.f;
            if (gp < SPOS)
                v = cache_k[((size_t)b*MAXSEQ + gp)*DMODEL + kk + jl];
            else if (gp < KVLEN)
                v = g_k[(size_t)(b*SEQ + gp - SPOS)*DMODEL + kk + jl];
            Ws[jl][p] = v;
        }
        __syncthreads();
#pragma unroll
        for (int j = 0; j < 16; j++) {
            float av[4];
#pragma unroll
            for (int mi = 0; mi < 4; mi++) av[mi] = As[kk+j][ty*4+mi];
            float4 w0 = *(const float4*)&Ws[j][tx*8];
            float4 w1 = *(const float4*)&Ws[j][tx*8+4];
            float wv[8] = {w0.x,w0.y,w0.z,w0.w,w1.x,w1.y,w1.z,w1.w};
#pragma unroll
            for (int mi = 0; mi < 4; mi++)
#pragma unroll
                for (int ni = 0; ni < 8; ni++)
                    acc[mi][ni] += av[mi]*wv[ni];
        }
    }

#pragma unroll
    for (int mi = 0; mi < 4; mi++) {
        int q = ty*4 + mi;
#pragma unroll
        for (int ni = 0; ni < 8; ni++) {
            int p = p0 + tx*8 + ni;
            if (p < KVLEN) {
                float s = acc[mi][ni]*ATT_SCALE;
                size_t idx = (size_t)(b*SEQ + q)*KVLEN + p;
                weight_out[idx] = s;
                g_sc[idx] = s + mask[q*KVLEN + p];
            }
        }
    }
}

// ============================================================
// Row softmax over g_sc (in place). 128 blocks (one per row), 256 threads.
// ============================================================
__global__ void __launch_bounds__(256) softmax_kernel()
{
    const int row = blockIdx.x;
    float* s = g_sc + (size_t)row*KVLEN;
    __shared__ float red[256];
    const int tid = threadIdx.x;

    float m = -1e30f;
    for (int i = tid; i < KVLEN; i += 256) m = fmaxf(m, s[i]);
    red[tid] = m; __syncthreads();
    for (int st = 128; st > 0; st >>= 1) {
        if (tid < st) red[tid] = fmaxf(red[tid], red[tid+st]);
        __syncthreads();
    }
    m = red[0]; __syncthreads();

    float sum = 0.f;
    for (int i = tid; i < KVLEN; i += 256) {
        float e = __expf(s[i] - m);
        s[i] = e;
        sum += e;
    }
    red[tid] = sum; __syncthreads();
    for (int st = 128; st > 0; st >>= 1) {
        if (tid < st) red[tid] += red[tid+st];
        __syncthreads();
    }
    float inv = 1.f/red[0];
    __syncthreads();
    for (int i = tid; i < KVLEN; i += 256) s[i] *= inv;
}

// ============================================================
// PV: partial[b][vt][sp][q][c] = sum_{kv in chunk sp} probs[b][q][kv]*V[b][kv][vt*128+c]
// grid (NSPLIT, 4, 8), 64 threads, micro 4x8, BK=32.
// ============================================================
__global__ void __launch_bounds__(64) pv_kernel(const float* __restrict__ cache_v)
{
    __shared__ float Ps[32][17];    // Ps[j][q]
    __shared__ float Vs[32][132];   // Vs[j][c]
    const int tid = threadIdx.x;
    const int tx = tid & 15, ty = tid >> 4;
    const int lane = tid & 31, w = tid >> 5;
    const int sp = blockIdx.x, vt = blockIdx.y, b = blockIdx.z;
    const int vd0 = vt*128;
    const int kv0 = sp*512;
    const int kvend = (kv0 + 512 < KVLEN) ? kv0 + 512 : KVLEN;
    const float* probs = g_sc + (size_t)b*SEQ*KVLEN;

    float acc[4][8];
#pragma unroll
    for (int a = 0; a < 4; a++)
#pragma unroll
        for (int c = 0; c < 8; c++) acc[a][c] = 0.f;

    for (int kk = kv0; kk < kvend; kk += 32) {
        __syncthreads();
        {
            int kv = kk + lane;
            for (int q = w; q < 16; q += 2)
                Ps[lane][q] = (kv < KVLEN) ? probs[(size_t)q*KVLEN + kv] : 0.f;
        }
        for (int r = w; r < 32; r += 2) {
            int kv = kk + r;
            float4 val = make_float4(0.f,0.f,0.f,0.f);
            if (kv < KVLEN) {
                const float* vrow = (kv < SPOS)
                    ? cache_v + ((size_t)b*MAXSEQ + kv)*DMODEL
                    : g_v + (size_t)(b*SEQ + kv - SPOS)*DMODEL;
                val = *(const float4*)&vrow[vd0 + lane*4];
            }
            *(float4*)&Vs[r][lane*4] = val;
        }
        __syncthreads();
#pragma unroll
        for (int j = 0; j < 32; j++) {
            float av[4];
#pragma unroll
            for (int mi = 0; mi < 4; mi++) av[mi] = Ps[j][ty*4+mi];
            float4 v0 = *(const float4*)&Vs[j][tx*8];
            float4 v1 = *(const float4*)&Vs[j][tx*8+4];
            float vv[8] = {v0.x,v0.y,v0.z,v0.w,v1.x,v1.y,v1.z,v1.w};
#pragma unroll
            for (int mi = 0; mi < 4; mi++)
#pragma unroll
                for (int ni = 0; ni < 8; ni++)
                    acc[mi][ni] += av[mi]*vv[ni];
        }
    }

    float* dst = g_part + ((((size_t)b*4 + vt)*NSPLIT + sp)*SEQ)*128;
#pragma unroll
    for (int mi = 0; mi < 4; mi++) {
        size_t base = (size_t)(ty*4 + mi)*128 + tx*8;
        float4 o0 = make_float4(acc[mi][0],acc[mi][1],acc[mi][2],acc[mi][3]);
        float4 o1 = make_float4(acc[mi][4],acc[mi][5],acc[mi][6],acc[mi][7]);
        *(float4*)&dst[base]   = o0;
        *(float4*)&dst[base+4] = o1;
    }
}

// ============================================================
// Reduce split-KV partials into g_att. 65536 elems.
// ============================================================
__global__ void __launch_bounds__(256) reduce_kernel()
{
    int i = blockIdx.x*256 + threadIdx.x;
    int vd = i & 511, row = i >> 9;
    int b = row >> 4, q = row & 15;
    int vt = vd >> 7, c = vd & 127;
    float s = 0.f;
#pragma unroll
    for (int sp = 0; sp < NSPLIT; sp++)
        s += g_part[((((size_t)b*4 + vt)*NSPLIT + sp)*SEQ + q)*128 + c];
    g_att[i] = s;
}

// ============================================================
extern "C" void kernel_launch(void* const* d_in, const int* in_sizes, int n_in,
                              void* d_out, int out_size)
{
    const float* x       = (const float*)d_in[0];
    // d_in[1] = start_pos (int32, fixed 4096 by problem setup)
    const float* mask    = (const float*)d_in[2];
    const float* Wq      = (const float*)d_in[3];
    const float* Wk      = (const float*)d_in[4];
    const float* Wv      = (const float*)d_in[5];
    const float* Wo      = (const float*)d_in[6];
    const float* cache_k = (const float*)d_in[7];
    const float* cache_v = (const float*)d_in[8];

    float* out    = (float*)d_out;                 // [128][512]
    float* weight = out + (size_t)NROWS*DMODEL;    // [128][4112]

    void *pq, *pk, *pv, *patt;
    cudaGetSymbolAddress(&pq,  g_q);
    cudaGetSymbolAddress(&pk,  g_k);
    cudaGetSymbolAddress(&pv,  g_v);
    cudaGetSymbolAddress(&patt, g_att);

    dim3 gproj(4, 8);   // 512/128 n-tiles, 128/16 m-tiles
    gemm16x128<<<gproj, 64>>>(x, Wq, (float*)pq, DMODEL);
    gemm16x128<<<gproj, 64>>>(x, Wk, (float*)pk, DMODEL);
    gemm16x128<<<gproj, 64>>>(x, Wv, (float*)pv, DMODEL);

    scores_kernel<<<dim3(33, 8), 64>>>(cache_k, mask, weight);
    softmax_kernel<<<NROWS, 256>>>();
    pv_kernel<<<dim3(NSPLIT, 4, BSZ), 64>>>(cache_v);
    reduce_kernel<<<256, 256>>>();

    gemm16x128<<<gproj, 64>>>((const float*)patt, Wo, out, DMODEL);
}

// round 2
// speedup vs baseline: 6.4322x; 6.4322x over previous
#include <cuda_runtime.h>
#include <cstdint>

#define BSZ      8
#define SEQ      16
#define DMODEL   512
#define MAXSEQ   8192
#define SPOS     4096
#define KVLEN    4112
#define NROWS    (BSZ*SEQ)        // 128
#define ATT_SCALE 0.0625f         // (512/2)^-0.5
#define NSPLIT   16               // kv splits of 256 (last +16)

typedef unsigned long long u64;

__device__ __forceinline__ u64 ffma2(u64 a, u64 b, u64 c){
    u64 d; asm("fma.rn.f32x2 %0,%1,%2,%3;" : "=l"(d) : "l"(a), "l"(b), "l"(c)); return d;
}
__device__ __forceinline__ u64 bcast2(float x){
    u64 d; asm("mov.b64 %0,{%1,%1};" : "=l"(d) : "f"(x)); return d;
}
__device__ __forceinline__ float2 unpk(u64 v){
    float2 f; asm("mov.b64 {%0,%1},%2;" : "=f"(f.x), "=f"(f.y) : "l"(v)); return f;
}
__device__ __forceinline__ void cp16(uint32_t s, const void* g, int sz){
    asm volatile("cp.async.cg.shared.global [%0], [%1], 16, %2;" :: "r"(s), "l"(g), "r"(sz));
}
__device__ __forceinline__ void cpcommit(){ asm volatile("cp.async.commit_group;"); }
template<int N> __device__ __forceinline__ void cpwait(){ asm volatile("cp.async.wait_group %0;" :: "n"(N)); }

// ---- scratch ----
__device__ float g_q[NROWS*DMODEL];
__device__ float g_k[NROWS*DMODEL];
__device__ float g_v[NROWS*DMODEL];
__device__ float g_sc[(size_t)NROWS*KVLEN];
__device__ float g_part[(size_t)BSZ*4*NSPLIT*SEQ*128];   // 4MB
__device__ float g_att[NROWS*DMODEL];

// ============================================================
// gemm_wt: C[16m x 128e tile] = A[16x512] @ W[e][512]^T
// 128 threads: tx=tid&31 (4 cols), ty=tid>>5 (4 rows).
// W tile transpose-stored to smem; LDG prefetch overlaps compute.
// ============================================================
__global__ void __launch_bounds__(128) gemm_wt(
    const float* __restrict__ A, const float* __restrict__ W,
    float* __restrict__ C)
{
    __shared__ float As[16][DMODEL];   // natural; warp-uniform broadcast reads
    __shared__ float Ws[32][128];      // [k][e_local]
    const int tid = threadIdx.x;
    const int tx = tid & 31, ty = tid >> 5;
    const int e0 = blockIdx.x * 128, m0 = blockIdx.y * 16;

    { // load A tile flat (16x512 floats = 2048 float4)
        const float4* src = (const float4*)(A + (size_t)m0*DMODEL);
        float4* dst = (float4*)&As[0][0];
#pragma unroll
        for (int i = 0; i < 16; i++) dst[tid + i*128] = src[tid + i*128];
    }

    const float* wrow = W + (size_t)(e0 + tid)*DMODEL;   // each thread owns one e-row

    u64 acc[4][2];
#pragma unroll
    for (int mi = 0; mi < 4; mi++){ acc[mi][0] = 0ull; acc[mi][1] = 0ull; }

    float4 st[8];
#pragma unroll
    for (int j = 0; j < 8; j++) st[j] = ((const float4*)wrow)[j];
#pragma unroll
    for (int j = 0; j < 8; j++){
        Ws[j*4+0][tid] = st[j].x; Ws[j*4+1][tid] = st[j].y;
        Ws[j*4+2][tid] = st[j].z; Ws[j*4+3][tid] = st[j].w;
    }
    __syncthreads();

    for (int t = 0; t < 16; t++){
        if (t < 15){
            const float4* src = (const float4*)(wrow + (t+1)*32);
#pragma unroll
            for (int j = 0; j < 8; j++) st[j] = src[j];
        }
        const int kb = t*32;
#pragma unroll
        for (int k = 0; k < 32; k++){
            ulonglong2 w = *(const ulonglong2*)&Ws[k][tx*4];
#pragma unroll
            for (int mi = 0; mi < 4; mi++){
                u64 av = bcast2(As[ty*4+mi][kb+k]);
                acc[mi][0] = ffma2(av, w.x, acc[mi][0]);
                acc[mi][1] = ffma2(av, w.y, acc[mi][1]);
            }
        }
        if (t < 15){
            __syncthreads();
#pragma unroll
            for (int j = 0; j < 8; j++){
                Ws[j*4+0][tid] = st[j].x; Ws[j*4+1][tid] = st[j].y;
                Ws[j*4+2][tid] = st[j].z; Ws[j*4+3][tid] = st[j].w;
            }
            __syncthreads();
        }
    }

#pragma unroll
    for (int mi = 0; mi < 4; mi++){
        float2 lo = unpk(acc[mi][0]), hi = unpk(acc[mi][1]);
        float4 o = make_float4(lo.x, lo.y, hi.x, hi.y);
        *(float4*)&C[(size_t)(m0 + ty*4 + mi)*DMODEL + e0 + tx*4] = o;
    }
}

// ============================================================
// scores: dist[b][q][p], K piecewise (cache / fresh). Writes weight
// (pre-mask, scaled) and masked scores to g_sc. grid (33, 8).
// ============================================================
__global__ void __launch_bounds__(128) scores_v2(
    const float* __restrict__ cache_k, const float* __restrict__ mask,
    float* __restrict__ weight)
{
    __shared__ float As[16][DMODEL];
    __shared__ float Ws[32][128];
    const int tid = threadIdx.x;
    const int tx = tid & 31, ty = tid >> 5;
    const int b = blockIdx.y;
    const int p0 = blockIdx.x * 128;

    {
        const float4* src = (const float4*)(g_q + (size_t)b*SEQ*DMODEL);
        float4* dst = (float4*)&As[0][0];
#pragma unroll
        for (int i = 0; i < 16; i++) dst[tid + i*128] = src[tid + i*128];
    }

    const int gp = p0 + tid;
    const float* krow;
    bool valid = true;
    if (gp < SPOS)          krow = cache_k + ((size_t)b*MAXSEQ + gp)*DMODEL;
    else if (gp < KVLEN)    krow = g_k + (size_t)(b*SEQ + gp - SPOS)*DMODEL;
    else                    { krow = cache_k; valid = false; }

    u64 acc[4][2];
#pragma unroll
    for (int mi = 0; mi < 4; mi++){ acc[mi][0] = 0ull; acc[mi][1] = 0ull; }

    float4 st[8];
#pragma unroll
    for (int j = 0; j < 8; j++) st[j] = valid ? ((const float4*)krow)[j] : make_float4(0.f,0.f,0.f,0.f);
#pragma unroll
    for (int j = 0; j < 8; j++){
        Ws[j*4+0][tid] = st[j].x; Ws[j*4+1][tid] = st[j].y;
        Ws[j*4+2][tid] = st[j].z; Ws[j*4+3][tid] = st[j].w;
    }
    __syncthreads();

    for (int t = 0; t < 16; t++){
        if (t < 15){
            const float4* src = (const float4*)(krow + (t+1)*32);
#pragma unroll
            for (int j = 0; j < 8; j++) st[j] = valid ? src[j] : make_float4(0.f,0.f,0.f,0.f);
        }
        const int kb = t*32;
#pragma unroll
        for (int k = 0; k < 32; k++){
            ulonglong2 w = *(const ulonglong2*)&Ws[k][tx*4];
#pragma unroll
            for (int mi = 0; mi < 4; mi++){
                u64 av = bcast2(As[ty*4+mi][kb+k]);
                acc[mi][0] = ffma2(av, w.x, acc[mi][0]);
                acc[mi][1] = ffma2(av, w.y, acc[mi][1]);
            }
        }
        if (t < 15){
            __syncthreads();
#pragma unroll
            for (int j = 0; j < 8; j++){
                Ws[j*4+0][tid] = st[j].x; Ws[j*4+1][tid] = st[j].y;
                Ws[j*4+2][tid] = st[j].z; Ws[j*4+3][tid] = st[j].w;
            }
            __syncthreads();
        }
    }

    const int p = p0 + tx*4;
    if (p < KVLEN){
#pragma unroll
        for (int mi = 0; mi < 4; mi++){
            const int q = ty*4 + mi;
            float2 lo = unpk(acc[mi][0]), hi = unpk(acc[mi][1]);
            float4 s4 = make_float4(lo.x*ATT_SCALE, lo.y*ATT_SCALE, hi.x*ATT_SCALE, hi.y*ATT_SCALE);
            size_t idx = (size_t)(b*SEQ + q)*KVLEN + p;
            *(float4*)&weight[idx] = s4;
            float4 m4 = *(const float4*)&mask[(size_t)q*KVLEN + p];
            float4 o = make_float4(s4.x+m4.x, s4.y+m4.y, s4.z+m4.z, s4.w+m4.w);
            *(float4*)&g_sc[idx] = o;
        }
    }
}

// ============================================================
// row softmax (in place on g_sc)
// ============================================================
__global__ void __launch_bounds__(256) softmax_kernel()
{
    const int row = blockIdx.x;
    float* s = g_sc + (size_t)row*KVLEN;
    __shared__ float red[256];
    const int tid = threadIdx.x;

    float m = -1e30f;
    for (int i = tid; i < KVLEN; i += 256) m = fmaxf(m, s[i]);
    red[tid] = m; __syncthreads();
    for (int st = 128; st > 0; st >>= 1){
        if (tid < st) red[tid] = fmaxf(red[tid], red[tid+st]);
        __syncthreads();
    }
    m = red[0]; __syncthreads();

    float sum = 0.f;
    for (int i = tid; i < KVLEN; i += 256){
        float e = __expf(s[i] - m);
        s[i] = e; sum += e;
    }
    red[tid] = sum; __syncthreads();
    for (int st = 128; st > 0; st >>= 1){
        if (tid < st) red[tid] += red[tid+st];
        __syncthreads();
    }
    float inv = 1.f/red[0];
    __syncthreads();
    for (int i = tid; i < KVLEN; i += 256) s[i] *= inv;
}

// ============================================================
// PV split-K: partial[b][vt][s][16][128]. grid (16, 4, 8).
// cp.async double-buffered pipeline; natural V layout, no transpose.
// ============================================================
__global__ void __launch_bounds__(128) pv_v2(const float* __restrict__ cache_v)
{
    __shared__ float Ps[2][16][32];
    __shared__ float Vs[2][32][128];
    const int tid = threadIdx.x;
    const int tx = tid & 31, ty = tid >> 5;
    const int s = blockIdx.x, vt = blockIdx.y, b = blockIdx.z;
    const int kv0 = s*256;
    const int T = (s == NSPLIT-1) ? 9 : 8;
    const float* probs = g_sc + (size_t)b*SEQ*KVLEN;

    // per-thread cp.async assignments
    const int pq  = tid >> 3, pseg = tid & 7;      // Ps: one 16B chunk
    uint32_t ps_base = (uint32_t)__cvta_generic_to_shared(&Ps[0][0][0]);
    uint32_t vs_base = (uint32_t)__cvta_generic_to_shared(&Vs[0][0][0]);

    auto issue = [&](int t){
        const int buf = t & 1;
        const int kvb = kv0 + t*32;
        // Ps chunk
        {
            int kvp = kvb + pseg*4;
            int sz = (kvp < KVLEN) ? 16 : 0;
            uint32_t dst = ps_base + (uint32_t)(buf*16*32 + pq*32 + pseg*4)*4u;
            cp16(dst, probs + (size_t)pq*KVLEN + kvp, sz);
        }
        // Vs chunks: 8 per thread
#pragma unroll
        for (int j = 0; j < 8; j++){
            int c = tid + j*128;
            int row = c >> 5, col = (c & 31)*4;
            int kv = kvb + row;
            const float* src;
            int sz = 16;
            if (kv < SPOS)        src = cache_v + ((size_t)b*MAXSEQ + kv)*DMODEL + vt*128 + col;
            else if (kv < KVLEN)  src = g_v + (size_t)(b*SEQ + kv - SPOS)*DMODEL + vt*128 + col;
            else                  { src = cache_v; sz = 0; }
            uint32_t dst = vs_base + (uint32_t)(buf*32*128 + row*128 + col)*4u;
            cp16(dst, src, sz);
        }
        cpcommit();
    };

    u64 acc[4][2];
#pragma unroll
    for (int mi = 0; mi < 4; mi++){ acc[mi][0] = 0ull; acc[mi][1] = 0ull; }

    issue(0);
    for (int t = 0; t < T; t++){
        if (t+1 < T) issue(t+1);
        if (t+1 < T) cpwait<1>(); else cpwait<0>();
        __syncthreads();
        const int buf = t & 1;
#pragma unroll
        for (int k = 0; k < 32; k++){
            ulonglong2 w = *(const ulonglong2*)&Vs[buf][k][tx*4];
#pragma unroll
            for (int mi = 0; mi < 4; mi++){
                u64 av = bcast2(Ps[buf][ty*4+mi][k]);
                acc[mi][0] = ffma2(av, w.x, acc[mi][0]);
                acc[mi][1] = ffma2(av, w.y, acc[mi][1]);
            }
        }
        __syncthreads();
    }

    float* dst = g_part + (((size_t)(b*4 + vt)*NSPLIT + s)*SEQ)*128;
#pragma unroll
    for (int mi = 0; mi < 4; mi++){
        float2 lo = unpk(acc[mi][0]), hi = unpk(acc[mi][1]);
        float4 o = make_float4(lo.x, lo.y, hi.x, hi.y);
        *(float4*)&dst[(size_t)(ty*4 + mi)*128 + tx*4] = o;
    }
}

// ============================================================
__global__ void __launch_bounds__(256) reduce_kernel()
{
    int i = blockIdx.x*256 + threadIdx.x;
    int vd = i & 511, row = i >> 9;
    int b = row >> 4, q = row & 15;
    int vt = vd >> 7, c = vd & 127;
    float sum = 0.f;
#pragma unroll
    for (int s = 0; s < NSPLIT; s++)
        sum += g_part[(((size_t)(b*4 + vt)*NSPLIT + s)*SEQ + q)*128 + c];
    g_att[(size_t)(b*SEQ + q)*DMODEL + vd] = sum;
}

// ============================================================
extern "C" void kernel_launch(void* const* d_in, const int* in_sizes, int n_in,
                              void* d_out, int out_size)
{
    const float* x       = (const float*)d_in[0];
    const float* mask    = (const float*)d_in[2];
    const float* Wq      = (const float*)d_in[3];
    const float* Wk      = (const float*)d_in[4];
    const float* Wv      = (const float*)d_in[5];
    const float* Wo      = (const float*)d_in[6];
    const float* cache_k = (const float*)d_in[7];
    const float* cache_v = (const float*)d_in[8];

    float* out    = (float*)d_out;
    float* weight = out + (size_t)NROWS*DMODEL;

    void *pq, *pk, *pv, *patt;
    cudaGetSymbolAddress(&pq,  g_q);
    cudaGetSymbolAddress(&pk,  g_k);
    cudaGetSymbolAddress(&pv,  g_v);
    cudaGetSymbolAddress(&patt, g_att);

    dim3 gproj(4, 8);   // 512/128 e-tiles, 128/16 m-tiles
    gemm_wt<<<gproj, 128>>>(x, Wq, (float*)pq);
    gemm_wt<<<gproj, 128>>>(x, Wk, (float*)pk);
    gemm_wt<<<gproj, 128>>>(x, Wv, (float*)pv);

    scores_v2<<<dim3(33, 8), 128>>>(cache_k, mask, weight);
    softmax_kernel<<<NROWS, 256>>>();
    pv_v2<<<dim3(NSPLIT, 4, BSZ), 128>>>(cache_v);
    reduce_kernel<<<256, 256>>>();

    gemm_wt<<<gproj, 128>>>((const float*)patt, Wo, out);
}

// round 3
// speedup vs baseline: 9.8548x; 1.5321x over previous
#include <cuda_runtime.h>
#include <cstdint>

#define BSZ      8
#define SEQ      16
#define DMODEL   512
#define MAXSEQ   8192
#define SPOS     4096
#define KVLEN    4112
#define NROWS    (BSZ*SEQ)        // 128
#define ATT_SCALE 0.0625f         // (512/2)^-0.5
#define NSPLIT   32               // kv splits of 128 (last +16)
#define KHALF    256              // scores k-split
#define KCH      16               // k per chunk in scores
#define NCH      (KHALF/KCH)      // 16 chunks
#define PSTRIDE  4224             // padded p stride (33*128)

typedef unsigned long long u64;

__device__ __forceinline__ u64 ffma2(u64 a, u64 b, u64 c){
    u64 d; asm("fma.rn.f32x2 %0,%1,%2,%3;" : "=l"(d) : "l"(a), "l"(b), "l"(c)); return d;
}
__device__ __forceinline__ u64 bcast2(float x){
    u64 d; asm("mov.b64 %0,{%1,%1};" : "=l"(d) : "f"(x)); return d;
}
__device__ __forceinline__ float2 unpk(u64 v){
    float2 f; asm("mov.b64 {%0,%1},%2;" : "=f"(f.x), "=f"(f.y) : "l"(v)); return f;
}
__device__ __forceinline__ void cp16(uint32_t s, const void* g, int sz){
    asm volatile("cp.async.cg.shared.global [%0], [%1], 16, %2;" :: "r"(s), "l"(g), "r"(sz));
}
__device__ __forceinline__ void cpcommit(){ asm volatile("cp.async.commit_group;"); }
template<int N> __device__ __forceinline__ void cpwait(){ asm volatile("cp.async.wait_group %0;" :: "n"(N)); }

// ---- scratch ----
__device__ float g_qT[BSZ*DMODEL*SEQ];                   // [b][d][q] transposed Q
__device__ float g_k[NROWS*DMODEL];
__device__ float g_v[NROWS*DMODEL];
__device__ float g_s1[(size_t)NROWS*PSTRIDE];            // scores partial (k 0..255)
__device__ float g_s2[(size_t)NROWS*PSTRIDE];            // scores partial (k 256..511)
__device__ float g_sc[(size_t)NROWS*PSTRIDE];            // probs
__device__ float g_part[(size_t)BSZ*4*NSPLIT*SEQ*128];   // PV partials
__device__ float g_att[NROWS*DMODEL];

// ============================================================
// gemm body (16m x 128e, W row-major [e][512]) — used for Wo and QKV.
// ============================================================
__device__ __forceinline__ void gemm_core(
    const float* __restrict__ A, const float* __restrict__ W,
    int m0, int e0, float (&Asm)[16][DMODEL], float (&Wsm)[32][128],
    u64 (&acc)[4][2])
{
    const int tid = threadIdx.x;
    const int tx = tid & 31, ty = tid >> 5;

    {
        const float4* src = (const float4*)(A + (size_t)m0*DMODEL);
        float4* dst = (float4*)&Asm[0][0];
#pragma unroll
        for (int i = 0; i < 16; i++) dst[tid + i*128] = src[tid + i*128];
    }

    const float* wrow = W + (size_t)(e0 + tid)*DMODEL;

#pragma unroll
    for (int mi = 0; mi < 4; mi++){ acc[mi][0] = 0ull; acc[mi][1] = 0ull; }

    float4 st[8];
#pragma unroll
    for (int j = 0; j < 8; j++) st[j] = ((const float4*)wrow)[j];
#pragma unroll
    for (int j = 0; j < 8; j++){
        Wsm[j*4+0][tid] = st[j].x; Wsm[j*4+1][tid] = st[j].y;
        Wsm[j*4+2][tid] = st[j].z; Wsm[j*4+3][tid] = st[j].w;
    }
    __syncthreads();

    for (int t = 0; t < 16; t++){
        if (t < 15){
            const float4* src = (const float4*)(wrow + (t+1)*32);
#pragma unroll
            for (int j = 0; j < 8; j++) st[j] = src[j];
        }
        const int kb = t*32;
#pragma unroll
        for (int k = 0; k < 32; k++){
            ulonglong2 w = *(const ulonglong2*)&Wsm[k][tx*4];
#pragma unroll
            for (int mi = 0; mi < 4; mi++){
                u64 av = bcast2(Asm[ty*4+mi][kb+k]);
                acc[mi][0] = ffma2(av, w.x, acc[mi][0]);
                acc[mi][1] = ffma2(av, w.y, acc[mi][1]);
            }
        }
        if (t < 15){
            __syncthreads();
#pragma unroll
            for (int j = 0; j < 8; j++){
                Wsm[j*4+0][tid] = st[j].x; Wsm[j*4+1][tid] = st[j].y;
                Wsm[j*4+2][tid] = st[j].z; Wsm[j*4+3][tid] = st[j].w;
            }
            __syncthreads();
        }
    }
}

// ---- Wo projection (natural output) ----
__global__ void __launch_bounds__(128) gemm_wt(
    const float* __restrict__ A, const float* __restrict__ W,
    float* __restrict__ C)
{
    __shared__ float Asm[16][DMODEL];
    __shared__ float Wsm[32][128];
    const int tid = threadIdx.x;
    const int tx = tid & 31, ty = tid >> 5;
    const int e0 = blockIdx.x * 128, m0 = blockIdx.y * 16;
    u64 acc[4][2];
    gemm_core(A, W, m0, e0, Asm, Wsm, acc);
#pragma unroll
    for (int mi = 0; mi < 4; mi++){
        float2 lo = unpk(acc[mi][0]), hi = unpk(acc[mi][1]);
        float4 o = make_float4(lo.x, lo.y, hi.x, hi.y);
        *(float4*)&C[(size_t)(m0 + ty*4 + mi)*DMODEL + e0 + tx*4] = o;
    }
}

// ---- fused QKV: z=0 -> Q (transposed), z=1 -> K, z=2 -> V ----
__global__ void __launch_bounds__(128) qkv_kernel(
    const float* __restrict__ x,
    const float* __restrict__ Wq, const float* __restrict__ Wk, const float* __restrict__ Wv)
{
    __shared__ float Asm[16][DMODEL];
    __shared__ float Wsm[32][128];
    const int tid = threadIdx.x;
    const int tx = tid & 31, ty = tid >> 5;
    const int e0 = blockIdx.x * 128, m0 = blockIdx.y * 16;
    const int z = blockIdx.z;
    const float* W = (z == 0) ? Wq : (z == 1) ? Wk : Wv;
    u64 acc[4][2];
    gemm_core(x, W, m0, e0, Asm, Wsm, acc);

    if (z == 0){
        const int b = blockIdx.y;
        float* qT = g_qT + (size_t)b*DMODEL*SEQ;
#pragma unroll
        for (int mi = 0; mi < 4; mi++){
            float2 lo = unpk(acc[mi][0]), hi = unpk(acc[mi][1]);
            float v[4] = {lo.x, lo.y, hi.x, hi.y};
            int q = ty*4 + mi;
#pragma unroll
            for (int j = 0; j < 4; j++)
                qT[(size_t)(e0 + tx*4 + j)*SEQ + q] = v[j];
        }
    } else {
        float* C = (z == 1) ? g_k : g_v;
#pragma unroll
        for (int mi = 0; mi < 4; mi++){
            float2 lo = unpk(acc[mi][0]), hi = unpk(acc[mi][1]);
            float4 o = make_float4(lo.x, lo.y, hi.x, hi.y);
            *(float4*)&C[(size_t)(m0 + ty*4 + mi)*DMODEL + e0 + tx*4] = o;
        }
    }
}

// ============================================================
// scores_v3: thread owns one p-row; K loaded coalesced (cp.async,
// natural [p][k] layout); Q k-major broadcast; f32x2 over q pairs.
// grid (33 p-tiles, 8 b, 2 k-halves), 128 threads.
// ============================================================
__global__ void __launch_bounds__(128) scores_v3(const float* __restrict__ cache_k)
{
    __shared__ alignas(16) float At[KHALF*SEQ];          // [k][q] 16KB
    __shared__ alignas(16) float Ws[2][128*(KCH+4)];     // [p][16k + pad] 20KB
    const int tid = threadIdx.x;
    const int p0 = blockIdx.x * 128;
    const int b  = blockIdx.y;
    const int z  = blockIdx.z;
    const int koff = z * KHALF;
    float* s_out = (z == 0 ? g_s1 : g_s2) + (size_t)b*SEQ*PSTRIDE;

    { // load Q^T slice: 4096 contiguous floats
        const float4* src = (const float4*)(g_qT + (size_t)b*DMODEL*SEQ + (size_t)koff*SEQ);
        float4* dst = (float4*)At;
#pragma unroll
        for (int i = 0; i < 8; i++) dst[tid + i*128] = src[tid + i*128];
    }

    uint32_t ws_base = (uint32_t)__cvta_generic_to_shared(&Ws[0][0]);
    const int lrow = tid >> 2;          // 0..31
    const int lcol = (tid & 3) * 4;     // 0,4,8,12

    auto issue = [&](int t){
        const int buf = t & 1;
#pragma unroll
        for (int j = 0; j < 4; j++){
            int row = lrow + j*32;
            int gp = p0 + row;
            const float* src;
            int sz = 16;
            if (gp < SPOS)       src = cache_k + ((size_t)b*MAXSEQ + gp)*DMODEL + koff + t*KCH + lcol;
            else if (gp < KVLEN) src = g_k + ((size_t)(b*SEQ + gp - SPOS))*DMODEL + koff + t*KCH + lcol;
            else                 { src = cache_k; sz = 0; }
            uint32_t dst = ws_base + (uint32_t)(buf*128*(KCH+4) + row*(KCH+4) + lcol)*4u;
            cp16(dst, src, sz);
        }
        cpcommit();
    };

    u64 acc[8];
#pragma unroll
    for (int i = 0; i < 8; i++) acc[i] = 0ull;

    issue(0);
    for (int t = 0; t < NCH; t++){
        if (t+1 < NCH) issue(t+1);
        if (t+1 < NCH) cpwait<1>(); else cpwait<0>();
        __syncthreads();
        const int buf = t & 1;
        const float* wrow = &Ws[buf][tid*(KCH+4)];
#pragma unroll
        for (int kg = 0; kg < KCH/4; kg++){
            float4 w4 = *(const float4*)&wrow[kg*4];
            float wv[4] = {w4.x, w4.y, w4.z, w4.w};
#pragma unroll
            for (int j = 0; j < 4; j++){
                const int kk = t*KCH + kg*4 + j;
                u64 wp = bcast2(wv[j]);
                ulonglong2 a0 = *(const ulonglong2*)&At[kk*SEQ];
                ulonglong2 a1 = *(const ulonglong2*)&At[kk*SEQ + 4];
                ulonglong2 a2 = *(const ulonglong2*)&At[kk*SEQ + 8];
                ulonglong2 a3 = *(const ulonglong2*)&At[kk*SEQ + 12];
                acc[0] = ffma2(a0.x, wp, acc[0]);
                acc[1] = ffma2(a0.y, wp, acc[1]);
                acc[2] = ffma2(a1.x, wp, acc[2]);
                acc[3] = ffma2(a1.y, wp, acc[3]);
                acc[4] = ffma2(a2.x, wp, acc[4]);
                acc[5] = ffma2(a2.y, wp, acc[5]);
                acc[6] = ffma2(a3.x, wp, acc[6]);
                acc[7] = ffma2(a3.y, wp, acc[7]);
            }
        }
        __syncthreads();
    }

    float* base = s_out + p0 + tid;
#pragma unroll
    for (int i = 0; i < 8; i++){
        float2 f = unpk(acc[i]);
        base[(size_t)(2*i)*PSTRIDE]   = f.x;
        base[(size_t)(2*i+1)*PSTRIDE] = f.y;
    }
}

// ============================================================
// softmax: combine k-split partials, scale, write weight (pre-mask),
// softmax(+mask) -> probs g_sc. Values held in registers across passes.
// ============================================================
__global__ void __launch_bounds__(256) softmax_v3(
    const float* __restrict__ mask, float* __restrict__ weight)
{
    const int row = blockIdx.x;
    const int q = row & 15;
    const int tid = threadIdx.x;
    const float4* s1 = (const float4*)(g_s1 + (size_t)row*PSTRIDE);
    const float4* s2 = (const float4*)(g_s2 + (size_t)row*PSTRIDE);
    const float4* mk = (const float4*)(mask + (size_t)q*KVLEN);
    float4* wout = (float4*)(weight + (size_t)row*KVLEN);
    float4* pout = (float4*)(g_sc + (size_t)row*PSTRIDE);
    const int N4 = KVLEN/4;   // 1028

    __shared__ float red[256];
    float4 vals[5];
    float m = -1e30f;
#pragma unroll
    for (int j = 0; j < 5; j++){
        int i = tid + j*256;
        if (i < N4){
            float4 a = s1[i], c = s2[i], mm = mk[i];
            float4 w;
            w.x = (a.x+c.x)*ATT_SCALE; w.y = (a.y+c.y)*ATT_SCALE;
            w.z = (a.z+c.z)*ATT_SCALE; w.w = (a.w+c.w)*ATT_SCALE;
            wout[i] = w;
            float4 d = make_float4(w.x+mm.x, w.y+mm.y, w.z+mm.z, w.w+mm.w);
            vals[j] = d;
            m = fmaxf(m, fmaxf(fmaxf(d.x,d.y), fmaxf(d.z,d.w)));
        }
    }
    red[tid] = m; __syncthreads();
    for (int st = 128; st > 0; st >>= 1){
        if (tid < st) red[tid] = fmaxf(red[tid], red[tid+st]);
        __syncthreads();
    }
    m = red[0]; __syncthreads();

    float sum = 0.f;
#pragma unroll
    for (int j = 0; j < 5; j++){
        int i = tid + j*256;
        if (i < N4){
            float4 d = vals[j];
            float4 e = make_float4(__expf(d.x-m), __expf(d.y-m), __expf(d.z-m), __expf(d.w-m));
            vals[j] = e;
            sum += e.x + e.y + e.z + e.w;
        }
    }
    red[tid] = sum; __syncthreads();
    for (int st = 128; st > 0; st >>= 1){
        if (tid < st) red[tid] += red[tid+st];
        __syncthreads();
    }
    float inv = 1.f/red[0];
#pragma unroll
    for (int j = 0; j < 5; j++){
        int i = tid + j*256;
        if (i < N4){
            float4 e = vals[j];
            pout[i] = make_float4(e.x*inv, e.y*inv, e.z*inv, e.w*inv);
        }
    }
}

// ============================================================
// PV split-K: grid (32, 4, 8). cp.async double-buffered.
// ============================================================
__global__ void __launch_bounds__(128) pv_v3(const float* __restrict__ cache_v)
{
    __shared__ alignas(16) float Ps[2][16][32];
    __shared__ alignas(16) float Vs[2][32][128];
    const int tid = threadIdx.x;
    const int tx = tid & 31, ty = tid >> 5;
    const int s = blockIdx.x, vt = blockIdx.y, b = blockIdx.z;
    const int kv0 = s*128;
    const int T = (s == NSPLIT-1) ? 5 : 4;
    const float* probs = g_sc + (size_t)b*SEQ*PSTRIDE;

    const int pq = tid >> 3, pseg = tid & 7;
    uint32_t ps_base = (uint32_t)__cvta_generic_to_shared(&Ps[0][0][0]);
    uint32_t vs_base = (uint32_t)__cvta_generic_to_shared(&Vs[0][0][0]);

    auto issue = [&](int t){
        const int buf = t & 1;
        const int kvb = kv0 + t*32;
        {
            int kvp = kvb + pseg*4;
            int sz = (kvp < KVLEN) ? 16 : 0;
            uint32_t dst = ps_base + (uint32_t)(buf*16*32 + pq*32 + pseg*4)*4u;
            cp16(dst, probs + (size_t)pq*PSTRIDE + kvp, sz);
        }
#pragma unroll
        for (int j = 0; j < 8; j++){
            int c = tid + j*128;
            int row = c >> 5, col = (c & 31)*4;
            int kv = kvb + row;
            const float* src;
            int sz = 16;
            if (kv < SPOS)        src = cache_v + ((size_t)b*MAXSEQ + kv)*DMODEL + vt*128 + col;
            else if (kv < KVLEN)  src = g_v + (size_t)(b*SEQ + kv - SPOS)*DMODEL + vt*128 + col;
            else                  { src = cache_v; sz = 0; }
            uint32_t dst = vs_base + (uint32_t)(buf*32*128 + row*128 + col)*4u;
            cp16(dst, src, sz);
        }
        cpcommit();
    };

    u64 acc[4][2];
#pragma unroll
    for (int mi = 0; mi < 4; mi++){ acc[mi][0] = 0ull; acc[mi][1] = 0ull; }

    issue(0);
    for (int t = 0; t < T; t++){
        if (t+1 < T) issue(t+1);
        if (t+1 < T) cpwait<1>(); else cpwait<0>();
        __syncthreads();
        const int buf = t & 1;
#pragma unroll
        for (int k = 0; k < 32; k++){
            ulonglong2 w = *(const ulonglong2*)&Vs[buf][k][tx*4];
#pragma unroll
            for (int mi = 0; mi < 4; mi++){
                u64 av = bcast2(Ps[buf][ty*4+mi][k]);
                acc[mi][0] = ffma2(av, w.x, acc[mi][0]);
                acc[mi][1] = ffma2(av, w.y, acc[mi][1]);
            }
        }
        __syncthreads();
    }

    float* dst = g_part + (((size_t)(b*4 + vt)*NSPLIT + s)*SEQ)*128;
#pragma unroll
    for (int mi = 0; mi < 4; mi++){
        float2 lo = unpk(acc[mi][0]), hi = unpk(acc[mi][1]);
        float4 o = make_float4(lo.x, lo.y, hi.x, hi.y);
        *(float4*)&dst[(size_t)(ty*4 + mi)*128 + tx*4] = o;
    }
}

// ============================================================
__global__ void __launch_bounds__(256) reduce_kernel()
{
    int i = blockIdx.x*256 + threadIdx.x;
    int vd = i & 511, row = i >> 9;
    int b = row >> 4, q = row & 15;
    int vt = vd >> 7, c = vd & 127;
    float sum = 0.f;
#pragma unroll
    for (int s = 0; s < NSPLIT; s++)
        sum += g_part[(((size_t)(b*4 + vt)*NSPLIT + s)*SEQ + q)*128 + c];
    g_att[(size_t)(b*SEQ + q)*DMODEL + vd] = sum;
}

// ============================================================
extern "C" void kernel_launch(void* const* d_in, const int* in_sizes, int n_in,
                              void* d_out, int out_size)
{
    const float* x       = (const float*)d_in[0];
    const float* mask    = (const float*)d_in[2];
    const float* Wq      = (const float*)d_in[3];
    const float* Wk      = (const float*)d_in[4];
    const float* Wv      = (const float*)d_in[5];
    const float* Wo      = (const float*)d_in[6];
    const float* cache_k = (const float*)d_in[7];
    const float* cache_v = (const float*)d_in[8];

    float* out    = (float*)d_out;
    float* weight = out + (size_t)NROWS*DMODEL;

    void* patt;
    cudaGetSymbolAddress(&patt, g_att);

    qkv_kernel<<<dim3(4, 8, 3), 128>>>(x, Wq, Wk, Wv);
    scores_v3<<<dim3(33, 8, 2), 128>>>(cache_k);
    softmax_v3<<<NROWS, 256>>>(mask, weight);
    pv_v3<<<dim3(NSPLIT, 4, BSZ), 128>>>(cache_v);
    reduce_kernel<<<256, 256>>>();
    gemm_wt<<<dim3(4, 8), 128>>>((const float*)patt, Wo, out);
}